// round 11
// baseline (speedup 1.0000x reference)
#include <cuda_runtime.h>
#include <cuda_bf16.h>
#include <cstdint>

// Problem dims (fixed by the dataset)
#define DB 32
#define DT 32
#define DK 196
#define DH 512
#define DA 512

#define OUT_ALPHA_OFF (DB*DT*DH)            // 524288
#define OUT_BETA_OFF  (DB*DT*DH + DB*DT*DK) // 724992

// Scratch (allocation-free rule: __device__ globals)
__device__ float g_cv[DB*DK*DA];   // att_feats @ Wv   (6272 x 512)
__device__ float g_cg[DB*DT*DA];   // hiddens   @ Wg   (1024 x 512)
__device__ float g_cs[DB*DT*DA];   // sentinel  @ Ws   (1024 x 512)
__device__ float g_zt[DB*DT*DK];   // logits           (1024 x 196)
__device__ __nv_bfloat16 g_wt_hi[3*512*512];   // W^T hi, [wsel][n][k]
__device__ __nv_bfloat16 g_wt_lo[3*512*512];   // W^T lo
__device__ __nv_bfloat16 g_a_hi[8320*512];     // A hi: att|hid|sen rows
__device__ __nv_bfloat16 g_a_lo[8320*512];     // A lo

// ---------------------------------------------------------------------------
// helpers
// ---------------------------------------------------------------------------
__device__ __forceinline__ uint32_t smem_to_u32(const void* p) {
    uint32_t a;
    asm("{ .reg .u64 t; cvta.to.shared.u64 t, %1; cvt.u32.u64 %0, t; }"
        : "=r"(a) : "l"(p));
    return a;
}
#define SWZ(o) ((o) ^ (((o) >> 3) & 0x70))

__device__ __forceinline__ void ldsm_x4(uint32_t* r, uint32_t addr) {
    asm volatile("ldmatrix.sync.aligned.m8n8.x4.shared.b16 {%0,%1,%2,%3}, [%4];"
        : "=r"(r[0]), "=r"(r[1]), "=r"(r[2]), "=r"(r[3]) : "r"(addr));
}
__device__ __forceinline__ void mma16816(float* c, const uint32_t* a,
                                         const uint32_t* b) {
    asm volatile(
        "mma.sync.aligned.m16n8k16.row.col.f32.bf16.bf16.f32 "
        "{%0,%1,%2,%3}, {%4,%5,%6,%7}, {%8,%9}, {%0,%1,%2,%3};"
        : "+f"(c[0]), "+f"(c[1]), "+f"(c[2]), "+f"(c[3])
        : "r"(a[0]), "r"(a[1]), "r"(a[2]), "r"(a[3]), "r"(b[0]), "r"(b[1]));
}
__device__ __forceinline__ void cpa16(uint32_t dst, const __nv_bfloat16* src) {
    asm volatile("cp.async.cg.shared.global [%0], [%1], 16;"
        :: "r"(dst), "l"(src));
}
__device__ __forceinline__ void fma2(unsigned long long& c,
                                     unsigned long long a,
                                     unsigned long long b) {
    asm("fma.rn.f32x2 %0, %1, %2, %0;" : "+l"(c) : "l"(a), "l"(b));
}
__device__ __forceinline__ unsigned long long pack2(float a, float b) {
    unsigned long long d;
    asm("mov.b64 %0, {%1, %2};" : "=l"(d) : "f"(a), "f"(b));
    return d;
}
__device__ __forceinline__ float lo2(unsigned long long v) {
    float a; unsigned hi;
    asm("mov.b64 {%0, %1}, %2;" : "=f"(a), "=r"(hi) : "l"(v));
    return a;
}
__device__ __forceinline__ float hi2(unsigned long long v) {
    unsigned lo; float b;
    asm("mov.b64 {%0, %1}, %2;" : "=r"(lo), "=f"(b) : "l"(v));
    return b;
}
__device__ __forceinline__ float tanh_approx(float x) {
    float y;
    asm("tanh.approx.f32 %0, %1;" : "=f"(y) : "f"(x));
    return y;
}

// ---------------------------------------------------------------------------
// Fused conversion kernel (one launch):
//  blocks [0, 4160)        : A hi/lo split (att|hid|sen rows -> g_a_hi/lo)
//  blocks [4160, 4160+768) : W transpose + hi/lo split -> g_wt_hi/lo
// ---------------------------------------------------------------------------
__global__ __launch_bounds__(256)
void conv_all(const float* __restrict__ att, const float* __restrict__ hid,
              const float* __restrict__ sen, const float* __restrict__ Wv,
              const float* __restrict__ Wg,  const float* __restrict__ Ws) {
    const int bid = blockIdx.x;
    const int tid = threadIdx.x;

    if (bid < 4160) {
        // ---- A split ----
        const int idx = bid * 256 + tid;        // float4 index
        const int row = idx >> 7;
        const int c4  = idx & 127;
        const float* src; int lrow;
        if (row < 6272)      { src = att; lrow = row; }
        else if (row < 7296) { src = hid; lrow = row - 6272; }
        else                 { src = sen; lrow = row - 7296; }
        float4 v = *(const float4*)(src + lrow * 512 + c4 * 4);
        __nv_bfloat162 h0, h1, l0, l1;
        h0.x = __float2bfloat16(v.x); h0.y = __float2bfloat16(v.y);
        h1.x = __float2bfloat16(v.z); h1.y = __float2bfloat16(v.w);
        l0.x = __float2bfloat16(v.x - __bfloat162float(h0.x));
        l0.y = __float2bfloat16(v.y - __bfloat162float(h0.y));
        l1.x = __float2bfloat16(v.z - __bfloat162float(h1.x));
        l1.y = __float2bfloat16(v.w - __bfloat162float(h1.y));
        __nv_bfloat162* dh = (__nv_bfloat162*)(g_a_hi + row * 512 + c4 * 4);
        __nv_bfloat162* dl = (__nv_bfloat162*)(g_a_lo + row * 512 + c4 * 4);
        dh[0] = h0; dh[1] = h1;
        dl[0] = l0; dl[1] = l1;
    } else {
        // ---- W transpose+split ----
        __shared__ float tile[32][33];
        const int bid2 = bid - 4160;            // 0..767
        const int wsel = bid2 >> 8;             // 0..2
        const int rem  = bid2 & 255;
        const int nb   = (rem & 15) * 32;
        const int kb   = (rem >> 4) * 32;
        const float* W = (wsel == 0) ? Wv : ((wsel == 1) ? Wg : Ws);
        const int tx = tid & 31, ty = tid >> 5;   // 32 x 8

#pragma unroll
        for (int i = 0; i < 32; i += 8)
            tile[ty + i][tx] = W[(kb + ty + i) * 512 + nb + tx];
        __syncthreads();

        __nv_bfloat16* oh = g_wt_hi + wsel * 262144;
        __nv_bfloat16* ol = g_wt_lo + wsel * 262144;
#pragma unroll
        for (int i = 0; i < 32; i += 8) {
            float v = tile[tx][ty + i];
            __nv_bfloat16 h = __float2bfloat16(v);
            oh[(nb + ty + i) * 512 + kb + tx] = h;
            ol[(nb + ty + i) * 512 + kb + tx] =
                __float2bfloat16(v - __bfloat162float(h));
        }
    }
}

// ---------------------------------------------------------------------------
// Fused HMMA GEMM: 512 threads (16 warps, 4/SMSP), warp tile 32x32,
// cp.async 3-stage pipeline (64KB/stage: AH|AL|BH|BL 16KB each).
// All operands pre-split bf16.  Split-bf16: C = Ah*Bh + Ah*Bl + Al*Bh.
// ---------------------------------------------------------------------------
#define STAGE_B 65536
#define GEMM_SMEM (3 * STAGE_B)

__global__ __launch_bounds__(512, 1)
void gemm_mma() {
    extern __shared__ __align__(1024) char smem[];
    const uint32_t sbase = smem_to_u32(smem);

    const int tid  = threadIdx.x;
    const int wid  = tid >> 5, lane = tid & 31;
    const int wm   = (wid & 3) * 32;    // warp m offset in tile
    const int wn   = (wid >> 2) * 32;   // warp n offset in tile

    // job decode: 260 = 196(cv) + 32(cg) + 32(cs)
    const int bid = blockIdx.x;
    float* Cg; int wsel, mt, nt, row_off;
    if (bid < 196)      { mt = bid >> 2; nt = bid & 3; Cg = g_cv; wsel = 0; row_off = 0; }
    else if (bid < 228) { int i = bid - 196; mt = i >> 2; nt = i & 3; Cg = g_cg; wsel = 1; row_off = 6272; }
    else                { int i = bid - 228; mt = i >> 2; nt = i & 3; Cg = g_cs; wsel = 2; row_off = 7296; }
    const int m0 = mt * 128, n0 = nt * 128;

    const __nv_bfloat16* AHg = g_a_hi + (row_off + m0) * 512;
    const __nv_bfloat16* ALg = g_a_lo + (row_off + m0) * 512;
    const __nv_bfloat16* BHg = g_wt_hi + wsel * 262144 + n0 * 512;
    const __nv_bfloat16* BLg = g_wt_lo + wsel * 262144 + n0 * 512;

    float c[2][4][4];
#pragma unroll
    for (int i = 0; i < 2; i++)
#pragma unroll
        for (int j = 0; j < 4; j++)
#pragma unroll
            for (int q = 0; q < 4; q++) c[i][j][q] = 0.f;

    // issue one stage of cp.async (8 x 16B per thread)
    auto issue = [&](int chunk, int st) {
        const int k0 = chunk * 64;
        const uint32_t sb = sbase + st * STAGE_B;
#pragma unroll
        for (int j = 0; j < 2; j++) {
            const int idx = tid + j * 512;       // 0..1023
            const int row = idx >> 3, ch = idx & 7;
            const uint32_t doff = SWZ((uint32_t)(row * 128 + ch * 16));
            const int soff = row * 512 + k0 + ch * 8;
            cpa16(sb + doff,          AHg + soff);
            cpa16(sb + 16384 + doff,  ALg + soff);
            cpa16(sb + 32768 + doff,  BHg + soff);
            cpa16(sb + 49152 + doff,  BLg + soff);
        }
        asm volatile("cp.async.commit_group;" ::: "memory");
    };

    issue(0, 0);
    issue(1, 1);

    for (int i = 0; i < 8; i++) {
        if (i + 2 < 8) issue(i + 2, (i + 2) % 3);
        if (i < 6)      asm volatile("cp.async.wait_group 2;" ::: "memory");
        else if (i == 6) asm volatile("cp.async.wait_group 1;" ::: "memory");
        else             asm volatile("cp.async.wait_group 0;" ::: "memory");
        __syncthreads();

        const uint32_t AH = sbase + (i % 3) * STAGE_B;
        const uint32_t AL = AH + 16384, BH = AH + 32768, BL = AH + 49152;
#pragma unroll
        for (int ks = 0; ks < 4; ks++) {
            const uint32_t kbA = (uint32_t)((ks * 16 + (lane >> 4) * 8) * 2);
            uint32_t ah[2][4], al[2][4];
#pragma unroll
            for (int mtile = 0; mtile < 2; mtile++) {
                uint32_t rowb = (uint32_t)((wm + mtile * 16 + (lane & 15)) * 128);
                uint32_t off  = SWZ(rowb + kbA);
                ldsm_x4(ah[mtile], AH + off);
                ldsm_x4(al[mtile], AL + off);
            }
            const uint32_t kbB = (uint32_t)((ks * 16 + ((lane >> 3) & 1) * 8) * 2);
            uint32_t bh[2][4], bl[2][4];
#pragma unroll
            for (int p = 0; p < 2; p++) {
                uint32_t nrow = (uint32_t)(wn + p * 16 + (lane & 7) +
                                           ((lane >> 4) & 1) * 8);
                uint32_t off = SWZ(nrow * 128 + kbB);
                ldsm_x4(bh[p], BH + off);
                ldsm_x4(bl[p], BL + off);
            }
#pragma unroll
            for (int mtile = 0; mtile < 2; mtile++) {
#pragma unroll
                for (int p = 0; p < 2; p++) {
#pragma unroll
                    for (int h = 0; h < 2; h++) {
                        float* cc = c[mtile][p * 2 + h];
                        mma16816(cc, ah[mtile], &bh[p][2 * h]);
                        mma16816(cc, ah[mtile], &bl[p][2 * h]);
                        mma16816(cc, al[mtile], &bh[p][2 * h]);
                    }
                }
            }
        }
        __syncthreads();
    }

    // epilogue
    const int r0 = lane >> 2, col = (lane & 3) * 2;
#pragma unroll
    for (int mtile = 0; mtile < 2; mtile++) {
#pragma unroll
        for (int ntl = 0; ntl < 4; ntl++) {
            float* cc = c[mtile][ntl];
            float* base = Cg + (m0 + wm + mtile * 16 + r0) * 512
                             + n0 + wn + ntl * 8 + col;
            *(float2*)(base)           = make_float2(cc[0], cc[1]);
            *(float2*)(base + 8 * 512) = make_float2(cc[2], cc[3]);
        }
    }
}

// ---------------------------------------------------------------------------
// z_t[b,t,k] = sum_a tanh(cv[b,k,a] + cg[b,t,a]) * wh[a]
// v4: t-tile 4 (16 f32-regs of accumulators) + __launch_bounds__(256,3)
// -> 3 blocks/SM (24 warps/SM, 6/SMSP).  KU=2 k-pair structure and float2
// width preserved from the measured-best R2 kernel.  Grid (2, 256).
// ---------------------------------------------------------------------------
__global__ __launch_bounds__(256, 3)
void z_kernel(const float* __restrict__ wh) {
    __shared__ __align__(16) float cgs[4][512];
    __shared__ __align__(16) float whs[512];

    const int tid = threadIdx.x;
    const int b   = blockIdx.y >> 3;          // 32 b
    const int t0  = (blockIdx.y & 7) * 4;     // 8 t-tiles of 4
    const int klo = blockIdx.x * 98;          // 2 k-chunks of 98

    const float* cgbase = g_cg + (b * DT + t0) * DA;
    for (int i = tid; i < 4 * 512; i += 256) ((float*)cgs)[i] = cgbase[i];
    for (int i = tid; i < 512; i += 256) whs[i] = wh[i];
    __syncthreads();

    const int w = tid >> 5, lane = tid & 31;

    for (int p = w; p < 49; p += 8) {         // 49 k-pairs per block
        const int k0 = klo + 2 * p;
        const float2* cv0 = (const float2*)(g_cv + (b * DK + k0) * DA);
        const float2* cv1 = cv0 + 256;        // next k row

        unsigned long long acc0[4], acc1[4];
#pragma unroll
        for (int tt = 0; tt < 4; tt++) { acc0[tt] = 0ull; acc1[tt] = 0ull; }

#pragma unroll 2
        for (int j = 0; j < 8; j++) {
            const int ai = lane + j * 32;     // float2 index (covers 2 a's)
            float2 v0 = cv0[ai];
            float2 v1 = cv1[ai];
            unsigned long long whd = *((const unsigned long long*)whs + ai);
#pragma unroll
            for (int tt = 0; tt < 4; tt++) {
                float2 c = *((const float2*)cgs[tt] + ai);
                unsigned long long t0p =
                    pack2(tanh_approx(v0.x + c.x), tanh_approx(v0.y + c.y));
                fma2(acc0[tt], t0p, whd);
                unsigned long long t1p =
                    pack2(tanh_approx(v1.x + c.x), tanh_approx(v1.y + c.y));
                fma2(acc1[tt], t1p, whd);
            }
        }

#pragma unroll
        for (int tt = 0; tt < 4; tt++) {
            float s0 = lo2(acc0[tt]) + hi2(acc0[tt]);
            float s1 = lo2(acc1[tt]) + hi2(acc1[tt]);
            s0 += __shfl_xor_sync(0xffffffffu, s0, 16);
            s1 += __shfl_xor_sync(0xffffffffu, s1, 16);
            s0 += __shfl_xor_sync(0xffffffffu, s0, 8);
            s1 += __shfl_xor_sync(0xffffffffu, s1, 8);
            s0 += __shfl_xor_sync(0xffffffffu, s0, 4);
            s1 += __shfl_xor_sync(0xffffffffu, s1, 4);
            s0 += __shfl_xor_sync(0xffffffffu, s0, 2);
            s1 += __shfl_xor_sync(0xffffffffu, s1, 2);
            s0 += __shfl_xor_sync(0xffffffffu, s0, 1);
            s1 += __shfl_xor_sync(0xffffffffu, s1, 1);
            if (lane == 0) {
                float* zr = g_zt + (b * DT + t0 + tt) * DK;
                zr[k0]     = s0;
                zr[k0 + 1] = s1;
            }
        }
    }
}

// ---------------------------------------------------------------------------
// Fused softmax + c_t + gate, v3: grid (16, 32) = (tg*4+hc, b), 256 thr.
// Block = (b, 8 t's, 128-float h-slice).  Warp w: softmax for row t0+w
// (redundant across the 4 h-slice blocks; alpha/beta written by hc==0 only),
// then warp w runs row t0+w's FULL k=196 GEMV over the block's h-slice.
// ---------------------------------------------------------------------------
__global__ __launch_bounds__(256)
void ct_k(const float* __restrict__ att, const float* __restrict__ sent,
          const float* __restrict__ wh, float* __restrict__ out) {
    __shared__ float al[8][DK];
    __shared__ float bsm[8];

    const int tid = threadIdx.x;
    const int b   = blockIdx.y;
    const int tg  = blockIdx.x >> 2;      // t-group 0..3
    const int hc  = blockIdx.x & 3;       // h-slice  0..3
    const int t0  = tg * 8;
    float* out_alpha = out + OUT_ALPHA_OFF;
    float* out_beta  = out + OUT_BETA_OFF;

    const int w = tid >> 5, lane = tid & 31;

    // --- per-warp softmax for row (b, t0+w) ---
    {
        const int row = b * DT + t0 + w;
        const float* cs = g_cs + row * DA;
        const float* cg = g_cg + row * DA;
        float ze = 0.f;
#pragma unroll
        for (int j = 0; j < 16; j++) {
            int a = lane + j * 32;
            ze = fmaf(tanh_approx(cs[a] + cg[a]), wh[a], ze);
        }
        ze += __shfl_xor_sync(0xffffffffu, ze, 16);
        ze += __shfl_xor_sync(0xffffffffu, ze, 8);
        ze += __shfl_xor_sync(0xffffffffu, ze, 4);
        ze += __shfl_xor_sync(0xffffffffu, ze, 2);
        ze += __shfl_xor_sync(0xffffffffu, ze, 1);

        const float* zr = g_zt + row * DK;
        float zv[7];
        float m = -1e30f;
#pragma unroll
        for (int j = 0; j < 7; j++) {
            int k = lane + j * 32;
            zv[j] = (k < DK) ? zr[k] : -1e30f;
            m = fmaxf(m, zv[j]);
        }
        m = fmaxf(m, __shfl_xor_sync(0xffffffffu, m, 16));
        m = fmaxf(m, __shfl_xor_sync(0xffffffffu, m, 8));
        m = fmaxf(m, __shfl_xor_sync(0xffffffffu, m, 4));
        m = fmaxf(m, __shfl_xor_sync(0xffffffffu, m, 2));
        m = fmaxf(m, __shfl_xor_sync(0xffffffffu, m, 1));

        float p[7];
        float S = 0.f;
#pragma unroll
        for (int j = 0; j < 7; j++) {
            p[j] = __expf(zv[j] - m);
            S += p[j];
        }
        S += __shfl_xor_sync(0xffffffffu, S, 16);
        S += __shfl_xor_sync(0xffffffffu, S, 8);
        S += __shfl_xor_sync(0xffffffffu, S, 4);
        S += __shfl_xor_sync(0xffffffffu, S, 2);
        S += __shfl_xor_sync(0xffffffffu, S, 1);

        float invS = 1.0f / S;
#pragma unroll
        for (int j = 0; j < 7; j++) {
            int k = lane + j * 32;
            if (k < DK) {
                float a = p[j] * invS;
                al[w][k] = a;
                if (hc == 0) out_alpha[row * DK + k] = a;
            }
        }

        float m2  = fmaxf(m, ze);
        float eb  = __expf(ze - m2);
        float den = S * __expf(m - m2) + eb;
        if (lane == 0) {
            float beta = eb / den;
            bsm[w] = beta;
            if (hc == 0) out_beta[row] = beta;
        }
    }
    __syncthreads();

    // --- c_t GEMV: warp w = row t0+w, full k range, h-slice hc*128 ---
    const int h = hc * 128 + lane * 4;
    const float* ap = att + (b * DK) * DH + h;
    const float* alw = al[w];

    float4 acc = make_float4(0.f, 0.f, 0.f, 0.f);
#pragma unroll 4
    for (int k = 0; k < DK; k++) {
        float4 af = *(const float4*)(ap + k * DH);
        float a = alw[k];
        acc.x = fmaf(a, af.x, acc.x);
        acc.y = fmaf(a, af.y, acc.y);
        acc.z = fmaf(a, af.z, acc.z);
        acc.w = fmaf(a, af.w, acc.w);
    }

    const int off = (b * DT + t0 + w) * DH + h;
    float4 s = *(const float4*)(sent + off);
    float bt = bsm[w];
    float4 r;
    r.x = fmaf(bt, s.x - acc.x, acc.x);
    r.y = fmaf(bt, s.y - acc.y, acc.y);
    r.z = fmaf(bt, s.z - acc.z, acc.z);
    r.w = fmaf(bt, s.w - acc.w, acc.w);
    *(float4*)(out + off) = r;
}

// ---------------------------------------------------------------------------
extern "C" void kernel_launch(void* const* d_in, const int* in_sizes, int n_in,
                              void* d_out, int out_size) {
    const float* att = (const float*)d_in[0];
    const float* hid = (const float*)d_in[1];
    const float* sen = (const float*)d_in[2];
    const float* Wv  = (const float*)d_in[3];
    const float* Wg  = (const float*)d_in[4];
    const float* Ws  = (const float*)d_in[5];
    const float* wh  = (const float*)d_in[6];
    float* out = (float*)d_out;

    static int smem_set = 0;
    if (!smem_set) {
        cudaFuncSetAttribute(gemm_mma,
                             cudaFuncAttributeMaxDynamicSharedMemorySize,
                             GEMM_SMEM);
        smem_set = 1;
    }

    conv_all<<<4928, 256>>>(att, hid, sen, Wv, Wg, Ws);
    gemm_mma<<<260, 512, GEMM_SMEM>>>();
    z_kernel<<<dim3(2, 256), 256>>>(wh);
    ct_k<<<dim3(16, 32), 256>>>(att, sen, wh, out);
}

// round 12
// speedup vs baseline: 1.0821x; 1.0821x over previous
#include <cuda_runtime.h>
#include <cuda_bf16.h>
#include <cstdint>

// Problem dims (fixed by the dataset)
#define DB 32
#define DT 32
#define DK 196
#define DH 512
#define DA 512

#define OUT_ALPHA_OFF (DB*DT*DH)            // 524288
#define OUT_BETA_OFF  (DB*DT*DH + DB*DT*DK) // 724992

// Scratch (allocation-free rule: __device__ globals)
__device__ float g_cv[DB*DK*DA];   // att_feats @ Wv   (6272 x 512)
__device__ float g_cg[DB*DT*DA];   // hiddens   @ Wg   (1024 x 512)
__device__ float g_cs[DB*DT*DA];   // sentinel  @ Ws   (1024 x 512)
__device__ float g_zt[DB*DT*DK];   // logits           (1024 x 196)
__device__ __nv_bfloat16 g_wt_hi[3*512*512];   // W^T hi, [wsel][n][k]
__device__ __nv_bfloat16 g_wt_lo[3*512*512];   // W^T lo
__device__ __nv_bfloat16 g_a_hi[8320*512];     // A hi: att|hid|sen rows
__device__ __nv_bfloat16 g_a_lo[8320*512];     // A lo

// ---------------------------------------------------------------------------
// helpers
// ---------------------------------------------------------------------------
__device__ __forceinline__ uint32_t smem_to_u32(const void* p) {
    uint32_t a;
    asm("{ .reg .u64 t; cvta.to.shared.u64 t, %1; cvt.u32.u64 %0, t; }"
        : "=r"(a) : "l"(p));
    return a;
}
#define SWZ(o) ((o) ^ (((o) >> 3) & 0x70))

__device__ __forceinline__ void ldsm_x4(uint32_t* r, uint32_t addr) {
    asm volatile("ldmatrix.sync.aligned.m8n8.x4.shared.b16 {%0,%1,%2,%3}, [%4];"
        : "=r"(r[0]), "=r"(r[1]), "=r"(r[2]), "=r"(r[3]) : "r"(addr));
}
__device__ __forceinline__ void mma16816(float* c, const uint32_t* a,
                                         const uint32_t* b) {
    asm volatile(
        "mma.sync.aligned.m16n8k16.row.col.f32.bf16.bf16.f32 "
        "{%0,%1,%2,%3}, {%4,%5,%6,%7}, {%8,%9}, {%0,%1,%2,%3};"
        : "+f"(c[0]), "+f"(c[1]), "+f"(c[2]), "+f"(c[3])
        : "r"(a[0]), "r"(a[1]), "r"(a[2]), "r"(a[3]), "r"(b[0]), "r"(b[1]));
}
__device__ __forceinline__ void cpa16(uint32_t dst, const __nv_bfloat16* src) {
    asm volatile("cp.async.cg.shared.global [%0], [%1], 16;"
        :: "r"(dst), "l"(src));
}
__device__ __forceinline__ void fma2(unsigned long long& c,
                                     unsigned long long a,
                                     unsigned long long b) {
    asm("fma.rn.f32x2 %0, %1, %2, %0;" : "+l"(c) : "l"(a), "l"(b));
}
__device__ __forceinline__ unsigned long long pack2(float a, float b) {
    unsigned long long d;
    asm("mov.b64 %0, {%1, %2};" : "=l"(d) : "f"(a), "f"(b));
    return d;
}
__device__ __forceinline__ float lo2(unsigned long long v) {
    float a; unsigned hi;
    asm("mov.b64 {%0, %1}, %2;" : "=f"(a), "=r"(hi) : "l"(v));
    return a;
}
__device__ __forceinline__ float hi2(unsigned long long v) {
    unsigned lo; float b;
    asm("mov.b64 {%0, %1}, %2;" : "=r"(lo), "=f"(b) : "l"(v));
    return b;
}
__device__ __forceinline__ float tanh_approx(float x) {
    float y;
    asm("tanh.approx.f32 %0, %1;" : "=f"(y) : "f"(x));
    return y;
}

// ---------------------------------------------------------------------------
// Fused conversion kernel (one launch):
//  blocks [0, 4160)        : A hi/lo split (att|hid|sen rows -> g_a_hi/lo)
//  blocks [4160, 4160+768) : W transpose + hi/lo split -> g_wt_hi/lo
// ---------------------------------------------------------------------------
__global__ __launch_bounds__(256)
void conv_all(const float* __restrict__ att, const float* __restrict__ hid,
              const float* __restrict__ sen, const float* __restrict__ Wv,
              const float* __restrict__ Wg,  const float* __restrict__ Ws) {
    const int bid = blockIdx.x;
    const int tid = threadIdx.x;

    if (bid < 4160) {
        // ---- A split ----
        const int idx = bid * 256 + tid;        // float4 index
        const int row = idx >> 7;
        const int c4  = idx & 127;
        const float* src; int lrow;
        if (row < 6272)      { src = att; lrow = row; }
        else if (row < 7296) { src = hid; lrow = row - 6272; }
        else                 { src = sen; lrow = row - 7296; }
        float4 v = *(const float4*)(src + lrow * 512 + c4 * 4);
        __nv_bfloat162 h0, h1, l0, l1;
        h0.x = __float2bfloat16(v.x); h0.y = __float2bfloat16(v.y);
        h1.x = __float2bfloat16(v.z); h1.y = __float2bfloat16(v.w);
        l0.x = __float2bfloat16(v.x - __bfloat162float(h0.x));
        l0.y = __float2bfloat16(v.y - __bfloat162float(h0.y));
        l1.x = __float2bfloat16(v.z - __bfloat162float(h1.x));
        l1.y = __float2bfloat16(v.w - __bfloat162float(h1.y));
        __nv_bfloat162* dh = (__nv_bfloat162*)(g_a_hi + row * 512 + c4 * 4);
        __nv_bfloat162* dl = (__nv_bfloat162*)(g_a_lo + row * 512 + c4 * 4);
        dh[0] = h0; dh[1] = h1;
        dl[0] = l0; dl[1] = l1;
    } else {
        // ---- W transpose+split ----
        __shared__ float tile[32][33];
        const int bid2 = bid - 4160;            // 0..767
        const int wsel = bid2 >> 8;             // 0..2
        const int rem  = bid2 & 255;
        const int nb   = (rem & 15) * 32;
        const int kb   = (rem >> 4) * 32;
        const float* W = (wsel == 0) ? Wv : ((wsel == 1) ? Wg : Ws);
        const int tx = tid & 31, ty = tid >> 5;   // 32 x 8

#pragma unroll
        for (int i = 0; i < 32; i += 8)
            tile[ty + i][tx] = W[(kb + ty + i) * 512 + nb + tx];
        __syncthreads();

        __nv_bfloat16* oh = g_wt_hi + wsel * 262144;
        __nv_bfloat16* ol = g_wt_lo + wsel * 262144;
#pragma unroll
        for (int i = 0; i < 32; i += 8) {
            float v = tile[tx][ty + i];
            __nv_bfloat16 h = __float2bfloat16(v);
            oh[(nb + ty + i) * 512 + kb + tx] = h;
            ol[(nb + ty + i) * 512 + kb + tx] =
                __float2bfloat16(v - __bfloat162float(h));
        }
    }
}

// ---------------------------------------------------------------------------
// Fused HMMA GEMM v3 (rate probe): tile 128x64, 512 threads (16 warps),
// warp tile 32x16, 2-stage cp.async pipeline (48KB/stage: AH16|AL16|BH8|BL8)
// -> 96KB smem, __launch_bounds__(512,2) = 2 blocks/SM, 32 warps/SM.
// K-chunk stays 64 so all 128B-row swizzle/ldsm math is unchanged.
// Split-bf16: C = Ah*Bh + Ah*Bl + Al*Bh.
// ---------------------------------------------------------------------------
#define STAGE_B 49152
#define GEMM_SMEM (2 * STAGE_B)

__global__ __launch_bounds__(512, 2)
void gemm_mma() {
    extern __shared__ __align__(1024) char smem[];
    const uint32_t sbase = smem_to_u32(smem);

    const int tid  = threadIdx.x;
    const int wid  = tid >> 5, lane = tid & 31;
    const int wm   = (wid & 3) * 32;    // warp m offset in tile
    const int wn   = (wid >> 2) * 16;   // warp n offset in tile

    // job decode: 520 = 392(cv) + 64(cg) + 64(cs); nt is 64-wide
    const int bid = blockIdx.x;
    float* Cg; int wsel, mt, nt, row_off;
    if (bid < 392)      { mt = bid >> 3; nt = bid & 7; Cg = g_cv; wsel = 0; row_off = 0; }
    else if (bid < 456) { int i = bid - 392; mt = i >> 3; nt = i & 7; Cg = g_cg; wsel = 1; row_off = 6272; }
    else                { int i = bid - 456; mt = i >> 3; nt = i & 7; Cg = g_cs; wsel = 2; row_off = 7296; }
    const int m0 = mt * 128, n0 = nt * 64;

    const __nv_bfloat16* AHg = g_a_hi + (row_off + m0) * 512;
    const __nv_bfloat16* ALg = g_a_lo + (row_off + m0) * 512;
    const __nv_bfloat16* BHg = g_wt_hi + wsel * 262144 + n0 * 512;
    const __nv_bfloat16* BLg = g_wt_lo + wsel * 262144 + n0 * 512;

    float c[2][2][4];   // [mtile][n-subtile][frag]
#pragma unroll
    for (int i = 0; i < 2; i++)
#pragma unroll
        for (int j = 0; j < 2; j++)
#pragma unroll
            for (int q = 0; q < 4; q++) c[i][j][q] = 0.f;

    // issue one stage: A = 1024 chunks (2/thread), B = 512 chunks (1/thread)
    auto issue = [&](int chunk, int st) {
        const int k0 = chunk * 64;
        const uint32_t sb = sbase + st * STAGE_B;
#pragma unroll
        for (int j = 0; j < 2; j++) {
            const int idx = tid + j * 512;       // 0..1023
            const int row = idx >> 3, ch = idx & 7;
            const uint32_t doff = SWZ((uint32_t)(row * 128 + ch * 16));
            const int soff = row * 512 + k0 + ch * 8;
            cpa16(sb + doff,         AHg + soff);
            cpa16(sb + 16384 + doff, ALg + soff);
        }
        {
            const int row = tid >> 3, ch = tid & 7;   // 64 rows x 8 chunks
            const uint32_t doff = SWZ((uint32_t)(row * 128 + ch * 16));
            const int soff = row * 512 + k0 + ch * 8;
            cpa16(sb + 32768 + doff, BHg + soff);
            cpa16(sb + 40960 + doff, BLg + soff);
        }
        asm volatile("cp.async.commit_group;" ::: "memory");
    };

    issue(0, 0);

    for (int i = 0; i < 8; i++) {
        if (i + 1 < 8) issue(i + 1, (i + 1) & 1);
        if (i < 7) asm volatile("cp.async.wait_group 1;" ::: "memory");
        else       asm volatile("cp.async.wait_group 0;" ::: "memory");
        __syncthreads();

        const uint32_t AH = sbase + (i & 1) * STAGE_B;
        const uint32_t AL = AH + 16384, BH = AH + 32768, BL = AH + 40960;
#pragma unroll
        for (int ks = 0; ks < 4; ks++) {
            const uint32_t kbA = (uint32_t)((ks * 16 + (lane >> 4) * 8) * 2);
            uint32_t ah[2][4], al[2][4];
#pragma unroll
            for (int mtile = 0; mtile < 2; mtile++) {
                uint32_t rowb = (uint32_t)((wm + mtile * 16 + (lane & 15)) * 128);
                uint32_t off  = SWZ(rowb + kbA);
                ldsm_x4(ah[mtile], AH + off);
                ldsm_x4(al[mtile], AL + off);
            }
            const uint32_t kbB = (uint32_t)((ks * 16 + ((lane >> 3) & 1) * 8) * 2);
            uint32_t bh[4], bl[4];
            {
                uint32_t nrow = (uint32_t)(wn + (lane & 7) +
                                           ((lane >> 4) & 1) * 8);
                uint32_t off = SWZ(nrow * 128 + kbB);
                ldsm_x4(bh, BH + off);
                ldsm_x4(bl, BL + off);
            }
#pragma unroll
            for (int mtile = 0; mtile < 2; mtile++) {
#pragma unroll
                for (int h = 0; h < 2; h++) {
                    float* cc = c[mtile][h];
                    mma16816(cc, ah[mtile], &bh[2 * h]);
                    mma16816(cc, ah[mtile], &bl[2 * h]);
                    mma16816(cc, al[mtile], &bh[2 * h]);
                }
            }
        }
        __syncthreads();
    }

    // epilogue
    const int r0 = lane >> 2, col = (lane & 3) * 2;
#pragma unroll
    for (int mtile = 0; mtile < 2; mtile++) {
#pragma unroll
        for (int ntl = 0; ntl < 2; ntl++) {
            float* cc = c[mtile][ntl];
            float* base = Cg + (m0 + wm + mtile * 16 + r0) * 512
                             + n0 + wn + ntl * 8 + col;
            *(float2*)(base)           = make_float2(cc[0], cc[1]);
            *(float2*)(base + 8 * 512) = make_float2(cc[2], cc[3]);
        }
    }
}

// ---------------------------------------------------------------------------
// z_t[b,t,k] = sum_a tanh(cv[b,k,a] + cg[b,t,a]) * wh[a]
// R2 structure (measured best, 3x validated) — DO NOT TOUCH.
// ---------------------------------------------------------------------------
__global__ __launch_bounds__(256, 2)
void z_kernel(const float* __restrict__ wh) {
    __shared__ __align__(16) float cgs[8][512];
    __shared__ __align__(16) float whs[512];

    const int tid = threadIdx.x;
    const int b   = blockIdx.y >> 2;
    const int t0  = (blockIdx.y & 3) * 8;
    const int klo = blockIdx.x * 98;          // 98 k's per block (even)

    const float* cgbase = g_cg + (b * DT + t0) * DA;
    for (int i = tid; i < 8 * 512; i += 256) ((float*)cgs)[i] = cgbase[i];
    for (int i = tid; i < 512; i += 256) whs[i] = wh[i];
    __syncthreads();

    const int w = tid >> 5, lane = tid & 31;

    for (int p = w; p < 49; p += 8) {         // 49 k-pairs per block
        const int k0 = klo + 2 * p;
        const float2* cv0 = (const float2*)(g_cv + (b * DK + k0) * DA);
        const float2* cv1 = cv0 + 256;        // next k row

        unsigned long long acc0[8], acc1[8];
#pragma unroll
        for (int tt = 0; tt < 8; tt++) { acc0[tt] = 0ull; acc1[tt] = 0ull; }

#pragma unroll 2
        for (int j = 0; j < 8; j++) {
            const int ai = lane + j * 32;     // float2 index (covers 2 a's)
            float2 v0 = cv0[ai];
            float2 v1 = cv1[ai];
            unsigned long long whd = *((const unsigned long long*)whs + ai);
#pragma unroll
            for (int tt = 0; tt < 8; tt++) {
                float2 c = *((const float2*)cgs[tt] + ai);
                unsigned long long t0p =
                    pack2(tanh_approx(v0.x + c.x), tanh_approx(v0.y + c.y));
                fma2(acc0[tt], t0p, whd);
                unsigned long long t1p =
                    pack2(tanh_approx(v1.x + c.x), tanh_approx(v1.y + c.y));
                fma2(acc1[tt], t1p, whd);
            }
        }

#pragma unroll
        for (int tt = 0; tt < 8; tt++) {
            float s0 = lo2(acc0[tt]) + hi2(acc0[tt]);
            float s1 = lo2(acc1[tt]) + hi2(acc1[tt]);
            s0 += __shfl_xor_sync(0xffffffffu, s0, 16);
            s1 += __shfl_xor_sync(0xffffffffu, s1, 16);
            s0 += __shfl_xor_sync(0xffffffffu, s0, 8);
            s1 += __shfl_xor_sync(0xffffffffu, s1, 8);
            s0 += __shfl_xor_sync(0xffffffffu, s0, 4);
            s1 += __shfl_xor_sync(0xffffffffu, s1, 4);
            s0 += __shfl_xor_sync(0xffffffffu, s0, 2);
            s1 += __shfl_xor_sync(0xffffffffu, s1, 2);
            s0 += __shfl_xor_sync(0xffffffffu, s0, 1);
            s1 += __shfl_xor_sync(0xffffffffu, s1, 1);
            if (lane == 0) {
                float* zr = g_zt + (b * DT + t0 + tt) * DK;
                zr[k0]     = s0;
                zr[k0 + 1] = s1;
            }
        }
    }
}

// ---------------------------------------------------------------------------
// Fused softmax + c_t + gate, v3: grid (16, 32) = (tg*4+hc, b), 256 thr.
// ---------------------------------------------------------------------------
__global__ __launch_bounds__(256)
void ct_k(const float* __restrict__ att, const float* __restrict__ sent,
          const float* __restrict__ wh, float* __restrict__ out) {
    __shared__ float al[8][DK];
    __shared__ float bsm[8];

    const int tid = threadIdx.x;
    const int b   = blockIdx.y;
    const int tg  = blockIdx.x >> 2;      // t-group 0..3
    const int hc  = blockIdx.x & 3;       // h-slice  0..3
    const int t0  = tg * 8;
    float* out_alpha = out + OUT_ALPHA_OFF;
    float* out_beta  = out + OUT_BETA_OFF;

    const int w = tid >> 5, lane = tid & 31;

    // --- per-warp softmax for row (b, t0+w) ---
    {
        const int row = b * DT + t0 + w;
        const float* cs = g_cs + row * DA;
        const float* cg = g_cg + row * DA;
        float ze = 0.f;
#pragma unroll
        for (int j = 0; j < 16; j++) {
            int a = lane + j * 32;
            ze = fmaf(tanh_approx(cs[a] + cg[a]), wh[a], ze);
        }
        ze += __shfl_xor_sync(0xffffffffu, ze, 16);
        ze += __shfl_xor_sync(0xffffffffu, ze, 8);
        ze += __shfl_xor_sync(0xffffffffu, ze, 4);
        ze += __shfl_xor_sync(0xffffffffu, ze, 2);
        ze += __shfl_xor_sync(0xffffffffu, ze, 1);

        const float* zr = g_zt + row * DK;
        float zv[7];
        float m = -1e30f;
#pragma unroll
        for (int j = 0; j < 7; j++) {
            int k = lane + j * 32;
            zv[j] = (k < DK) ? zr[k] : -1e30f;
            m = fmaxf(m, zv[j]);
        }
        m = fmaxf(m, __shfl_xor_sync(0xffffffffu, m, 16));
        m = fmaxf(m, __shfl_xor_sync(0xffffffffu, m, 8));
        m = fmaxf(m, __shfl_xor_sync(0xffffffffu, m, 4));
        m = fmaxf(m, __shfl_xor_sync(0xffffffffu, m, 2));
        m = fmaxf(m, __shfl_xor_sync(0xffffffffu, m, 1));

        float p[7];
        float S = 0.f;
#pragma unroll
        for (int j = 0; j < 7; j++) {
            p[j] = __expf(zv[j] - m);
            S += p[j];
        }
        S += __shfl_xor_sync(0xffffffffu, S, 16);
        S += __shfl_xor_sync(0xffffffffu, S, 8);
        S += __shfl_xor_sync(0xffffffffu, S, 4);
        S += __shfl_xor_sync(0xffffffffu, S, 2);
        S += __shfl_xor_sync(0xffffffffu, S, 1);

        float invS = 1.0f / S;
#pragma unroll
        for (int j = 0; j < 7; j++) {
            int k = lane + j * 32;
            if (k < DK) {
                float a = p[j] * invS;
                al[w][k] = a;
                if (hc == 0) out_alpha[row * DK + k] = a;
            }
        }

        float m2  = fmaxf(m, ze);
        float eb  = __expf(ze - m2);
        float den = S * __expf(m - m2) + eb;
        if (lane == 0) {
            float beta = eb / den;
            bsm[w] = beta;
            if (hc == 0) out_beta[row] = beta;
        }
    }
    __syncthreads();

    // --- c_t GEMV: warp w = row t0+w, full k range, h-slice hc*128 ---
    const int h = hc * 128 + lane * 4;
    const float* ap = att + (b * DK) * DH + h;
    const float* alw = al[w];

    float4 acc = make_float4(0.f, 0.f, 0.f, 0.f);
#pragma unroll 4
    for (int k = 0; k < DK; k++) {
        float4 af = *(const float4*)(ap + k * DH);
        float a = alw[k];
        acc.x = fmaf(a, af.x, acc.x);
        acc.y = fmaf(a, af.y, acc.y);
        acc.z = fmaf(a, af.z, acc.z);
        acc.w = fmaf(a, af.w, acc.w);
    }

    const int off = (b * DT + t0 + w) * DH + h;
    float4 s = *(const float4*)(sent + off);
    float bt = bsm[w];
    float4 r;
    r.x = fmaf(bt, s.x - acc.x, acc.x);
    r.y = fmaf(bt, s.y - acc.y, acc.y);
    r.z = fmaf(bt, s.z - acc.z, acc.z);
    r.w = fmaf(bt, s.w - acc.w, acc.w);
    *(float4*)(out + off) = r;
}

// ---------------------------------------------------------------------------
extern "C" void kernel_launch(void* const* d_in, const int* in_sizes, int n_in,
                              void* d_out, int out_size) {
    const float* att = (const float*)d_in[0];
    const float* hid = (const float*)d_in[1];
    const float* sen = (const float*)d_in[2];
    const float* Wv  = (const float*)d_in[3];
    const float* Wg  = (const float*)d_in[4];
    const float* Ws  = (const float*)d_in[5];
    const float* wh  = (const float*)d_in[6];
    float* out = (float*)d_out;

    static int smem_set = 0;
    if (!smem_set) {
        cudaFuncSetAttribute(gemm_mma,
                             cudaFuncAttributeMaxDynamicSharedMemorySize,
                             GEMM_SMEM);
        smem_set = 1;
    }

    conv_all<<<4928, 256>>>(att, hid, sen, Wv, Wg, Ws);
    gemm_mma<<<520, 512, GEMM_SMEM>>>();
    z_kernel<<<dim3(2, 128), 256>>>(wh);
    ct_k<<<dim3(16, 32), 256>>>(att, sen, wh, out);
}